// round 12
// baseline (speedup 1.0000x reference)
#include <cuda_runtime.h>
#include <cuda_fp16.h>
#include <cstdint>

// ============================================================
// out[b,n] = sum_{c,p} x[b,c,p]*mask[p,c,n]*ro[c,n]
//          = A(256 x 82944) @ W(82944 x 2000),  k = p*64+c
//   A[b,k] = fp16(x[b,c,p])                  (pack kernel)
//   W[k,n] = fp16(mask_flat[k,n]*ro[k&63,n]*1024)  (built on the
//            fly inside the GEMM; output scaled by 1/1024)
// R12: occupancy experiment. CTA tile 128m x 128n (was 256x128),
//      __launch_bounds__(256,2) -> 2 CTAs/SM, 4 warps/SMSP
//      (was 2) to hide LDS/LDG latency. B build/ldmask reverted
//      to the R8 blocked mapping (best measured). Two no-op
//      kernels shift the ncu capture slot onto the GEMM.
// GEMM: mma.sync.m16n8k16 f32-accum, KTILE=32,
//      grid 16(n) x 2(m) x 9(split-K) = 288 CTAs = one wave.
// ============================================================

constexpr int BB   = 256;
constexpr int CCH  = 64;
constexpr int PPX  = 1296;
constexpr int NN   = 2000;
constexpr int NPAD = 2048;
constexpr long long KT_TOT = 82944;

constexpr int KSPLIT = 9;
constexpr int KSLICE = 9216;                  // 82944/9, divisible by 64
constexpr int KTILE  = 32;
constexpr int NKT    = KSLICE / KTILE;        // 288
constexpr int MTILE  = 128;
constexpr int NTILE  = 128;
constexpr int NTX    = 16;                    // 2048/128

constexpr int SA = 40;                        // A smem stride (halves): 80B rows, ldmatrix-clean
constexpr int SB = 34;                        // B smem stride (halves): 68B rows, conflict-free b32 frag loads
constexpr int A_ST = MTILE * SA;              // halves per A stage (5120)
constexpr int B_ST = NTILE * SB;              // halves per B stage (4352)
constexpr int SM_A_BYTES  = 2 * A_ST * 2;     // 20480
constexpr int SM_B_BYTES  = 2 * B_ST * 2;     // 17408
constexpr int SM_RO_BYTES = 64 * 128 * 4;     // 32768
constexpr int SMEM_TOTAL  = SM_A_BYTES + SM_B_BYTES + SM_RO_BYTES;  // 70656

// ------------- scratch (device globals; no runtime allocs allowed) ----------
__device__ __half g_Ah[(size_t)BB * KT_TOT];               // 42.5 MB
__device__ float  g_part[(size_t)KSPLIT * BB * NPAD];      // 18.9 MB

// ----------------------------- helpers --------------------------------------
__device__ __forceinline__ uint32_t smem_u32(const void* p) {
    uint32_t a;
    asm("{ .reg .u64 t; cvta.to.shared.u64 t, %1; cvt.u32.u64 %0, t; }"
        : "=r"(a) : "l"(p));
    return a;
}
__device__ __forceinline__ uint32_t lds_u32(uint32_t a) {
    uint32_t v;
    asm volatile("ld.shared.b32 %0, [%1];" : "=r"(v) : "r"(a));
    return v;
}
#define STS_U32(addr, v) \
    asm volatile("st.shared.b32 [%0], %1;" :: "r"(addr), "r"(v) : "memory")
#define CP_A16(dst, src) \
    asm volatile("cp.async.cg.shared.global [%0], [%1], 16;" :: "r"(dst), "l"(src))
#define CP_COMMIT() asm volatile("cp.async.commit_group;" ::: "memory")
#define CP_WAIT0()  asm volatile("cp.async.wait_group 0;" ::: "memory")
#define LDSM4(r0, r1, r2, r3, addr) \
    asm volatile("ldmatrix.sync.aligned.m8n8.x4.shared.b16 {%0,%1,%2,%3}, [%4];" \
        : "=r"(r0), "=r"(r1), "=r"(r2), "=r"(r3) : "r"(addr))
#define MMA16816(d0, d1, d2, d3, a0, a1, a2, a3, b0, b1) \
    asm volatile("mma.sync.aligned.m16n8k16.row.col.f32.f16.f16.f32 " \
        "{%0,%1,%2,%3}, {%4,%5,%6,%7}, {%8,%9}, {%0,%1,%2,%3};" \
        : "+f"(d0), "+f"(d1), "+f"(d2), "+f"(d3) \
        : "r"(a0), "r"(a1), "r"(a2), "r"(a3), "r"(b0), "r"(b1))

// ------------------ dummy kernels (shift ncu capture slot onto gemm) --------
__global__ void warm_a_kernel() {}
__global__ void warm_b_kernel() {}

// ------------------ kernel 1: pack x -> Ah[b][p*64+c] (fp16) ----------------
__global__ void pack_x_kernel(const float* __restrict__ x) {
    __shared__ float s[64][65];
    int b = blockIdx.y;
    int p0 = blockIdx.x * 64;
    int tid = threadIdx.x;
    const float* xb = x + (size_t)b * (CCH * PPX);
    #pragma unroll
    for (int it = 0; it < 16; it++) {
        int t = tid + it * 256;
        int c = t >> 6, i = t & 63, p = p0 + i;
        s[c][i] = (p < PPX) ? xb[c * PPX + p] : 0.f;
    }
    __syncthreads();
    __half* ab = g_Ah + (size_t)b * KT_TOT;
    #pragma unroll
    for (int it = 0; it < 16; it++) {
        int t = tid + it * 256;
        int i = t >> 6, c = t & 63, p = p0 + i;
        if (p < PPX) ab[p * 64 + c] = __float2half_rn(s[c][i]);
    }
}

// ------------------ kernel 2: fused fp16 mma.sync GEMM ----------------------
__global__ void __launch_bounds__(256, 2)
gemm_kernel(const float* __restrict__ mask, const float* __restrict__ ro) {
    extern __shared__ __align__(16) unsigned char smraw[];
    __half* As  = reinterpret_cast<__half*>(smraw);
    __half* Bsm = reinterpret_cast<__half*>(smraw + SM_A_BYTES);
    float*  ros = reinterpret_cast<float*>(smraw + SM_A_BYTES + SM_B_BYTES);

    int tid = threadIdx.x, w = tid >> 5, l = tid & 31;
    int n0 = blockIdx.x * NTILE;
    int m0 = blockIdx.y * MTILE;
    long long kbase = (long long)blockIdx.z * KSLICE;

    // preload ros[c][n'] = ro[c][n0+n'] * 1024  (64 x 128 fp32 = 32 KB)
    for (int idx = tid; idx < 64 * 32; idx += 256) {
        int c = idx >> 5, nq4 = idx & 31;
        float4 v = make_float4(0.f, 0.f, 0.f, 0.f);
        if (n0 + 4 * nq4 < NN) {
            float4 t = *reinterpret_cast<const float4*>(ro + (size_t)c * NN + n0 + 4 * nq4);
            v = make_float4(t.x * 1024.f, t.y * 1024.f, t.z * 1024.f, t.w * 1024.f);
        }
        reinterpret_cast<float4*>(ros)[idx] = v;
    }

    // B-build mapping (R8, best measured): thread (nq, kq) covers
    // n = n0+4nq..+3, k rows {2kq, 2kq+1, +16}
    int nq = tid & 31, kq = (tid >> 5) & 7;
    bool val = (n0 + 4 * nq) < NN;
    const float* mb = mask + kbase * NN + (n0 + 4 * nq);

    // A cp.async mapping: 2 threads per row (row = tid>>1), 32B each
    const __half* arow = g_Ah + (size_t)(m0 + (tid >> 1)) * KT_TOT + kbase
                              + (size_t)((tid & 1) * 16);
    uint32_t sbase = smem_u32(As);
    uint32_t adst  = sbase + (uint32_t)((tid >> 1) * (SA * 2) + (tid & 1) * 32);
    uint32_t bbase = smem_u32(Bsm);

    float4 mr[4];
    auto ldmask = [&](int kt) {
        #pragma unroll
        for (int it = 0; it < 2; it++) {
            int k0 = kt * KTILE + 2 * kq + 16 * it;
            if (val) {
                mr[2 * it]     = *reinterpret_cast<const float4*>(mb + (size_t)k0 * NN);
                mr[2 * it + 1] = *reinterpret_cast<const float4*>(mb + (size_t)(k0 + 1) * NN);
            } else {
                mr[2 * it] = make_float4(0.f, 0.f, 0.f, 0.f);
                mr[2 * it + 1] = make_float4(0.f, 0.f, 0.f, 0.f);
            }
        }
    };

    // build B tile (R8 layout [n][k], stride SB): b32 at (n, k0*2) =
    // {W[k0][n], W[k0+1][n]}
    auto buildB = [&](int kt, int s) {
        uint32_t bd = bbase + (uint32_t)(s * (B_ST * 2)) + (uint32_t)(4 * nq * SB * 2);
        const float* rp = ros + ((kt & 1) ? 32 * 128 : 0) + 4 * nq;
        #pragma unroll
        for (int it = 0; it < 2; it++) {
            int k0 = 2 * kq + 16 * it;
            float4 r0 = *reinterpret_cast<const float4*>(rp + k0 * 128);
            float4 r1 = *reinterpret_cast<const float4*>(rp + (k0 + 1) * 128);
            float4 w0 = mr[2 * it], w1 = mr[2 * it + 1];
            __half2 h0 = __floats2half2_rn(w0.x * r0.x, w1.x * r1.x);
            __half2 h1 = __floats2half2_rn(w0.y * r0.y, w1.y * r1.y);
            __half2 h2 = __floats2half2_rn(w0.z * r0.z, w1.z * r1.z);
            __half2 h3 = __floats2half2_rn(w0.w * r0.w, w1.w * r1.w);
            uint32_t a0 = bd + (uint32_t)(k0 * 2);
            STS_U32(a0,              *reinterpret_cast<uint32_t*>(&h0));
            STS_U32(a0 + SB * 2,     *reinterpret_cast<uint32_t*>(&h1));
            STS_U32(a0 + 2 * SB * 2, *reinterpret_cast<uint32_t*>(&h2));
            STS_U32(a0 + 3 * SB * 2, *reinterpret_cast<uint32_t*>(&h3));
        }
    };

    // ---------------- prologue ---------------------------------------------
    ldmask(0);
    CP_A16(adst,      arow);
    CP_A16(adst + 16, arow + 8);
    CP_COMMIT();

    __syncthreads();   // ros visible before first B build

    // fragment addressing: warp tile 32(m) x 64(n); 4 m-warps x 2 n-warps
    int wm = (w & 3) * 32, wn = (w >> 2) * 64;
    uint32_t aLdsm = sbase + (uint32_t)(((wm + (l & 15)) * SA + ((l & 16) ? 8 : 0)) * 2);
    uint32_t bfrag0 = bbase + (uint32_t)((wn + (l >> 2)) * SB * 2) + (uint32_t)(4 * (l & 3));

    float acc[2][8][4];
    #pragma unroll
    for (int i = 0; i < 2; i++)
        #pragma unroll
        for (int j = 0; j < 8; j++)
            #pragma unroll
            for (int q = 0; q < 4; q++) acc[i][j][q] = 0.f;

    // ---------------- main loop (double-buffer) ----------------------------
    for (int kt = 0; kt < NKT; kt++) {
        int s = kt & 1;

        buildB(kt, s);
        if (kt + 1 < NKT) ldmask(kt + 1);     // prefetch next mask tile into regs
        CP_WAIT0();                            // A[s] resident
        __syncthreads();                       // B[s] visible; prev-iter readers done

        if (kt + 1 < NKT) {                    // next A tile into other buffer
            uint32_t d2 = adst + (uint32_t)((s ^ 1) * (A_ST * 2));
            const __half* src = arow + (size_t)(kt + 1) * KTILE;
            CP_A16(d2,      src);
            CP_A16(d2 + 16, src + 8);
            CP_COMMIT();
        }

        // ---- MMA: warp tile 32(m) x 64(n), 2 ksteps of 16 ----------------
        uint32_t aS = aLdsm + (uint32_t)(s * (A_ST * 2));
        uint32_t bS = bfrag0 + (uint32_t)(s * (B_ST * 2));
        #pragma unroll
        for (int ks = 0; ks < 2; ks++) {
            uint32_t af[2][4];
            #pragma unroll
            for (int i = 0; i < 2; i++)
                LDSM4(af[i][0], af[i][1], af[i][2], af[i][3],
                      aS + (uint32_t)(i * 16 * SA * 2) + (uint32_t)(ks * 32));
            #pragma unroll
            for (int j = 0; j < 8; j++) {
                uint32_t ba = bS + (uint32_t)(j * 8 * SB * 2) + (uint32_t)(ks * 32);
                uint32_t b0 = lds_u32(ba);
                uint32_t b1 = lds_u32(ba + 16);
                #pragma unroll
                for (int i = 0; i < 2; i++)
                    MMA16816(acc[i][j][0], acc[i][j][1], acc[i][j][2], acc[i][j][3],
                             af[i][0], af[i][1], af[i][2], af[i][3], b0, b1);
            }
        }
    }

    // ---- epilogue: fp32 partials ------------------------------------------
    float* __restrict__ part = g_part + (size_t)blockIdx.z * BB * NPAD;
    int r0 = l >> 2, cq = 2 * (l & 3);
    #pragma unroll
    for (int i = 0; i < 2; i++) {
        #pragma unroll
        for (int j = 0; j < 8; j++) {
            int m = m0 + wm + 16 * i + r0;
            int n = wn + 8 * j + cq + n0;
            *reinterpret_cast<float2*>(part + (size_t)m * NPAD + n) =
                make_float2(acc[i][j][0], acc[i][j][1]);
            *reinterpret_cast<float2*>(part + (size_t)(m + 8) * NPAD + n) =
                make_float2(acc[i][j][2], acc[i][j][3]);
        }
    }
}

// ------------------ kernel 3: reduce partials -> out (x 1/1024) -------------
__global__ void reduce_kernel(float* __restrict__ out) {
    int id = blockIdx.x * 256 + threadIdx.x;          // id indexes (b, n4)
    int b = id / (NPAD / 4), n4 = id % (NPAD / 4);
    if (b >= BB) return;
    int n = n4 * 4;
    float4 s = make_float4(0.f, 0.f, 0.f, 0.f);
    #pragma unroll
    for (int ks = 0; ks < KSPLIT; ks++) {
        const float4 v = *reinterpret_cast<const float4*>(
            g_part + (size_t)ks * BB * NPAD + (size_t)b * NPAD + n);
        s.x += v.x; s.y += v.y; s.z += v.z; s.w += v.w;
    }
    const float inv = 1.f / 1024.f;
    float* o = out + (size_t)b * NN;
    if (n + 3 < NN) {
        o[n] = s.x * inv; o[n + 1] = s.y * inv; o[n + 2] = s.z * inv; o[n + 3] = s.w * inv;
    } else {
        if (n < NN)     o[n]     = s.x * inv;
        if (n + 1 < NN) o[n + 1] = s.y * inv;
        if (n + 2 < NN) o[n + 2] = s.z * inv;
        if (n + 3 < NN) o[n + 3] = s.w * inv;
    }
}

// ------------------------------- host ---------------------------------------
extern "C" void kernel_launch(void* const* d_in, const int* in_sizes, int n_in,
                              void* d_out, int out_size) {
    const float* x = nullptr;
    const float* mw = nullptr;
    const float* ro = nullptr;
    for (int i = 0; i < n_in; i++) {
        long long sz = in_sizes[i];
        if (sz == (long long)BB * CCH * PPX)      x  = (const float*)d_in[i];
        else if (sz == (long long)PPX * CCH * NN) mw = (const float*)d_in[i];
        else if (sz == (long long)CCH * NN)       ro = (const float*)d_in[i];
    }

    cudaFuncSetAttribute(gemm_kernel, cudaFuncAttributeMaxDynamicSharedMemorySize,
                         SMEM_TOTAL);

    warm_a_kernel<<<1, 32>>>();
    warm_b_kernel<<<1, 32>>>();
    pack_x_kernel<<<dim3(21, BB), 256>>>(x);
    gemm_kernel<<<dim3(NTX, BB / MTILE, KSPLIT), 256, SMEM_TOTAL>>>(mw, ro);
    reduce_kernel<<<(BB * (NPAD / 4) + 255) / 256, 256>>>((float*)d_out);
}

// round 13
// speedup vs baseline: 1.0382x; 1.0382x over previous
#include <cuda_runtime.h>
#include <cuda_fp16.h>
#include <cstdint>

// ============================================================
// out[b,n] = sum_{c,p} x[b,c,p]*mask[p,c,n]*ro[c,n]
//          = A(256 x 82944) @ W(82944 x 2000),  k = p*64+c
//   A[b,k] = fp16(x[b,c,p])                  (pack kernel)
//   W[k,n] = fp16(mask)*fp16(ro[k&63,n]*1024)  (built on the fly;
//            output scaled by 1/1024)
// R13 (on R12 base, ncu: L1=79% binding, tensor=33%, serialized):
//   1. ro moved from smem into 16 half2 registers (-16KB/iter L1,
//      -32KB smem, half2 build math)
//   2. intra-iter pipeline: MMA(kt) overlaps build(kt+1)+ldmask
//      (independent streams after the single barrier)
// GEMM: mma.sync.m16n8k16 f32-accum, CTA 128m x 128n, KTILE=32,
//      grid 16 x 2 x 9 = 288 CTAs, 2 CTAs/SM.
// ============================================================

constexpr int BB   = 256;
constexpr int CCH  = 64;
constexpr int PPX  = 1296;
constexpr int NN   = 2000;
constexpr int NPAD = 2048;
constexpr long long KT_TOT = 82944;

constexpr int KSPLIT = 9;
constexpr int KSLICE = 9216;                  // 82944/9
constexpr int KTILE  = 32;
constexpr int NKT    = KSLICE / KTILE;        // 288
constexpr int MTILE  = 128;
constexpr int NTILE  = 128;
constexpr int NTX    = 16;

constexpr int SA = 40;                        // A smem stride (halves)
constexpr int SB = 34;                        // B smem stride (halves)
constexpr int A_ST = MTILE * SA;              // 5120 halves / stage
constexpr int B_ST = NTILE * SB;              // 4352 halves / stage
constexpr int SM_A_BYTES  = 2 * A_ST * 2;     // 20480
constexpr int SM_B_BYTES  = 2 * B_ST * 2;     // 17408
constexpr int SMEM_TOTAL  = SM_A_BYTES + SM_B_BYTES;  // 37888

// ------------- scratch (device globals; no runtime allocs allowed) ----------
__device__ __half g_Ah[(size_t)BB * KT_TOT];               // 42.5 MB
__device__ float  g_part[(size_t)KSPLIT * BB * NPAD];      // 18.9 MB

// ----------------------------- helpers --------------------------------------
__device__ __forceinline__ uint32_t smem_u32(const void* p) {
    uint32_t a;
    asm("{ .reg .u64 t; cvta.to.shared.u64 t, %1; cvt.u32.u64 %0, t; }"
        : "=r"(a) : "l"(p));
    return a;
}
__device__ __forceinline__ uint32_t lds_u32(uint32_t a) {
    uint32_t v;
    asm volatile("ld.shared.b32 %0, [%1];" : "=r"(v) : "r"(a));
    return v;
}
#define STS_U32(addr, v) \
    asm volatile("st.shared.b32 [%0], %1;" :: "r"(addr), "r"(v) : "memory")
#define CP_A16(dst, src) \
    asm volatile("cp.async.cg.shared.global [%0], [%1], 16;" :: "r"(dst), "l"(src))
#define CP_COMMIT() asm volatile("cp.async.commit_group;" ::: "memory")
#define CP_WAIT0()  asm volatile("cp.async.wait_group 0;" ::: "memory")
#define LDSM4(r0, r1, r2, r3, addr) \
    asm volatile("ldmatrix.sync.aligned.m8n8.x4.shared.b16 {%0,%1,%2,%3}, [%4];" \
        : "=r"(r0), "=r"(r1), "=r"(r2), "=r"(r3) : "r"(addr))
#define MMA16816(d0, d1, d2, d3, a0, a1, a2, a3, b0, b1) \
    asm volatile("mma.sync.aligned.m16n8k16.row.col.f32.f16.f16.f32 " \
        "{%0,%1,%2,%3}, {%4,%5,%6,%7}, {%8,%9}, {%0,%1,%2,%3};" \
        : "+f"(d0), "+f"(d1), "+f"(d2), "+f"(d3) \
        : "r"(a0), "r"(a1), "r"(a2), "r"(a3), "r"(b0), "r"(b1))

// ------------------ dummy kernels (shift ncu capture slot onto gemm) --------
__global__ void warm_a_kernel() {}
__global__ void warm_b_kernel() {}

// ------------------ kernel 1: pack x -> Ah[b][p*64+c] (fp16) ----------------
__global__ void pack_x_kernel(const float* __restrict__ x) {
    __shared__ float s[64][65];
    int b = blockIdx.y;
    int p0 = blockIdx.x * 64;
    int tid = threadIdx.x;
    const float* xb = x + (size_t)b * (CCH * PPX);
    #pragma unroll
    for (int it = 0; it < 16; it++) {
        int t = tid + it * 256;
        int c = t >> 6, i = t & 63, p = p0 + i;
        s[c][i] = (p < PPX) ? xb[c * PPX + p] : 0.f;
    }
    __syncthreads();
    __half* ab = g_Ah + (size_t)b * KT_TOT;
    #pragma unroll
    for (int it = 0; it < 16; it++) {
        int t = tid + it * 256;
        int i = t >> 6, c = t & 63, p = p0 + i;
        if (p < PPX) ab[p * 64 + c] = __float2half_rn(s[c][i]);
    }
}

// ------------------ kernel 2: fused fp16 mma.sync GEMM ----------------------
__global__ void __launch_bounds__(256, 2)
gemm_kernel(const float* __restrict__ mask, const float* __restrict__ ro) {
    extern __shared__ __align__(16) unsigned char smraw[];
    __half* As  = reinterpret_cast<__half*>(smraw);
    __half* Bsm = reinterpret_cast<__half*>(smraw + SM_A_BYTES);

    int tid = threadIdx.x, w = tid >> 5, l = tid & 31;
    int n0 = blockIdx.x * NTILE;
    int m0 = blockIdx.y * MTILE;
    long long kbase = (long long)blockIdx.z * KSLICE;

    // B-build mapping (R8 blocked): thread (nq, kq) covers n = n0+4nq..+3,
    // k rows {2kq, 2kq+1, +16}
    int nq = tid & 31, kq = (tid >> 5) & 7;
    bool val = (n0 + 4 * nq) < NN;
    const float* mb = mask + kbase * NN + (n0 + 4 * nq);

    // readout in registers: rr0/rr1[it][q] = half2{ro[c0][n], ro[c1][n]}*1024
    // c0 = 2kq + 16it (+32 for rr1), c1 = c0+1, n = n0 + 4nq + q
    __half2 rr0[2][4], rr1[2][4];
    #pragma unroll
    for (int it = 0; it < 2; it++) {
        #pragma unroll
        for (int q = 0; q < 4; q++) {
            int n = n0 + 4 * nq + q;
            bool ok = (n < NN);
            int c0 = 2 * kq + 16 * it;
            float a0 = ok ? ro[(size_t)c0 * NN + n] * 1024.f : 0.f;
            float a1 = ok ? ro[(size_t)(c0 + 1) * NN + n] * 1024.f : 0.f;
            float b0 = ok ? ro[(size_t)(c0 + 32) * NN + n] * 1024.f : 0.f;
            float b1 = ok ? ro[(size_t)(c0 + 33) * NN + n] * 1024.f : 0.f;
            rr0[it][q] = __floats2half2_rn(a0, a1);
            rr1[it][q] = __floats2half2_rn(b0, b1);
        }
    }

    // A cp.async mapping: 2 threads per row (row = tid>>1), 32B each
    const __half* arow = g_Ah + (size_t)(m0 + (tid >> 1)) * KT_TOT + kbase
                              + (size_t)((tid & 1) * 16);
    uint32_t sbase = smem_u32(As);
    uint32_t adst  = sbase + (uint32_t)((tid >> 1) * (SA * 2) + (tid & 1) * 32);
    uint32_t bbase = smem_u32(Bsm);

    float4 mr[4];
    auto ldmask = [&](int kt) {
        #pragma unroll
        for (int it = 0; it < 2; it++) {
            int k0 = kt * KTILE + 2 * kq + 16 * it;
            if (val) {
                mr[2 * it]     = *reinterpret_cast<const float4*>(mb + (size_t)k0 * NN);
                mr[2 * it + 1] = *reinterpret_cast<const float4*>(mb + (size_t)(k0 + 1) * NN);
            } else {
                mr[2 * it] = make_float4(0.f, 0.f, 0.f, 0.f);
                mr[2 * it + 1] = make_float4(0.f, 0.f, 0.f, 0.f);
            }
        }
    };

    // build B tile (R8 layout [n][k], stride SB): b32 at (n, k0*2) =
    // {W[k0][n], W[k0+1][n]}.  rp selected at compile time per parity.
    auto buildB_impl = [&](int s, const __half2 (&rp)[2][4]) {
        uint32_t bd = bbase + (uint32_t)(s * (B_ST * 2)) + (uint32_t)(4 * nq * SB * 2);
        #pragma unroll
        for (int it = 0; it < 2; it++) {
            int k0 = 2 * kq + 16 * it;
            float4 w0 = mr[2 * it], w1 = mr[2 * it + 1];
            __half2 h0 = __hmul2(__floats2half2_rn(w0.x, w1.x), rp[it][0]);
            __half2 h1 = __hmul2(__floats2half2_rn(w0.y, w1.y), rp[it][1]);
            __half2 h2 = __hmul2(__floats2half2_rn(w0.z, w1.z), rp[it][2]);
            __half2 h3 = __hmul2(__floats2half2_rn(w0.w, w1.w), rp[it][3]);
            uint32_t a0 = bd + (uint32_t)(k0 * 2);
            STS_U32(a0,              *reinterpret_cast<uint32_t*>(&h0));
            STS_U32(a0 + SB * 2,     *reinterpret_cast<uint32_t*>(&h1));
            STS_U32(a0 + 2 * SB * 2, *reinterpret_cast<uint32_t*>(&h2));
            STS_U32(a0 + 3 * SB * 2, *reinterpret_cast<uint32_t*>(&h3));
        }
    };
    auto buildB = [&](int kt, int s) {
        if (kt & 1) buildB_impl(s, rr1);
        else        buildB_impl(s, rr0);
    };

    auto cpA = [&](int kt, int s) {
        uint32_t d = adst + (uint32_t)(s * (A_ST * 2));
        const __half* src = arow + (size_t)kt * KTILE;
        CP_A16(d,      src);
        CP_A16(d + 16, src + 8);
    };

    // ---------------- prologue ---------------------------------------------
    ldmask(0);
    cpA(0, 0); CP_COMMIT();
    buildB(0, 0);          // ro is in regs: no barrier needed before build
    ldmask(1);

    // fragment addressing: warp tile 32(m) x 64(n); 4 m-warps x 2 n-warps
    int wm = (w & 3) * 32, wn = (w >> 2) * 64;
    uint32_t aLdsm = sbase + (uint32_t)(((wm + (l & 15)) * SA + ((l & 16) ? 8 : 0)) * 2);
    uint32_t bfrag0 = bbase + (uint32_t)((wn + (l >> 2)) * SB * 2) + (uint32_t)(4 * (l & 3));

    float acc[2][8][4];
    #pragma unroll
    for (int i = 0; i < 2; i++)
        #pragma unroll
        for (int j = 0; j < 8; j++)
            #pragma unroll
            for (int q = 0; q < 4; q++) acc[i][j][q] = 0.f;

    // ---------------- main loop (pipelined: MMA(kt) || build(kt+1)) --------
    for (int kt = 0; kt < NKT; kt++) {
        int s = kt & 1;

        CP_WAIT0();          // A(kt) resident (committed last iter / prologue)
        __syncthreads();     // publish build(kt) STS + A(kt); fence prior readers

        if (kt + 1 < NKT) {
            cpA(kt + 1, s ^ 1); CP_COMMIT();   // into stage read by MMA(kt-1): safe
            buildB(kt + 1, s ^ 1);             // overlaps MMA(kt) below
        }
        if (kt + 2 < NKT) ldmask(kt + 2);      // refill mr (consumed by build above)

        // ---- MMA: warp tile 32(m) x 64(n), 2 ksteps of 16 ----------------
        uint32_t aS = aLdsm + (uint32_t)(s * (A_ST * 2));
        uint32_t bS = bfrag0 + (uint32_t)(s * (B_ST * 2));
        #pragma unroll
        for (int ks = 0; ks < 2; ks++) {
            uint32_t af[2][4];
            #pragma unroll
            for (int i = 0; i < 2; i++)
                LDSM4(af[i][0], af[i][1], af[i][2], af[i][3],
                      aS + (uint32_t)(i * 16 * SA * 2) + (uint32_t)(ks * 32));
            #pragma unroll
            for (int j = 0; j < 8; j++) {
                uint32_t ba = bS + (uint32_t)(j * 8 * SB * 2) + (uint32_t)(ks * 32);
                uint32_t b0 = lds_u32(ba);
                uint32_t b1 = lds_u32(ba + 16);
                #pragma unroll
                for (int i = 0; i < 2; i++)
                    MMA16816(acc[i][j][0], acc[i][j][1], acc[i][j][2], acc[i][j][3],
                             af[i][0], af[i][1], af[i][2], af[i][3], b0, b1);
            }
        }
    }

    // ---- epilogue: fp32 partials ------------------------------------------
    float* __restrict__ part = g_part + (size_t)blockIdx.z * BB * NPAD;
    int r0 = l >> 2, cq = 2 * (l & 3);
    #pragma unroll
    for (int i = 0; i < 2; i++) {
        #pragma unroll
        for (int j = 0; j < 8; j++) {
            int m = m0 + wm + 16 * i + r0;
            int n = wn + 8 * j + cq + n0;
            *reinterpret_cast<float2*>(part + (size_t)m * NPAD + n) =
                make_float2(acc[i][j][0], acc[i][j][1]);
            *reinterpret_cast<float2*>(part + (size_t)(m + 8) * NPAD + n) =
                make_float2(acc[i][j][2], acc[i][j][3]);
        }
    }
}

// ------------------ kernel 3: reduce partials -> out (x 1/1024) -------------
__global__ void reduce_kernel(float* __restrict__ out) {
    int id = blockIdx.x * 256 + threadIdx.x;          // id indexes (b, n4)
    int b = id / (NPAD / 4), n4 = id % (NPAD / 4);
    if (b >= BB) return;
    int n = n4 * 4;
    float4 s = make_float4(0.f, 0.f, 0.f, 0.f);
    #pragma unroll
    for (int ks = 0; ks < KSPLIT; ks++) {
        const float4 v = *reinterpret_cast<const float4*>(
            g_part + (size_t)ks * BB * NPAD + (size_t)b * NPAD + n);
        s.x += v.x; s.y += v.y; s.z += v.z; s.w += v.w;
    }
    const float inv = 1.f / 1024.f;
    float* o = out + (size_t)b * NN;
    if (n + 3 < NN) {
        o[n] = s.x * inv; o[n + 1] = s.y * inv; o[n + 2] = s.z * inv; o[n + 3] = s.w * inv;
    } else {
        if (n < NN)     o[n]     = s.x * inv;
        if (n + 1 < NN) o[n + 1] = s.y * inv;
        if (n + 2 < NN) o[n + 2] = s.z * inv;
        if (n + 3 < NN) o[n + 3] = s.w * inv;
    }
}

// ------------------------------- host ---------------------------------------
extern "C" void kernel_launch(void* const* d_in, const int* in_sizes, int n_in,
                              void* d_out, int out_size) {
    const float* x = nullptr;
    const float* mw = nullptr;
    const float* ro = nullptr;
    for (int i = 0; i < n_in; i++) {
        long long sz = in_sizes[i];
        if (sz == (long long)BB * CCH * PPX)      x  = (const float*)d_in[i];
        else if (sz == (long long)PPX * CCH * NN) mw = (const float*)d_in[i];
        else if (sz == (long long)CCH * NN)       ro = (const float*)d_in[i];
    }

    cudaFuncSetAttribute(gemm_kernel, cudaFuncAttributeMaxDynamicSharedMemorySize,
                         SMEM_TOTAL);

    warm_a_kernel<<<1, 32>>>();
    warm_b_kernel<<<1, 32>>>();
    pack_x_kernel<<<dim3(21, BB), 256>>>(x);
    gemm_kernel<<<dim3(NTX, BB / MTILE, KSPLIT), 256, SMEM_TOTAL>>>(mw, ro);
    reduce_kernel<<<(BB * (NPAD / 4) + 255) / 256, 256>>>((float*)d_out);
}

// round 15
// speedup vs baseline: 1.2128x; 1.1682x over previous
#include <cuda_runtime.h>
#include <cuda_fp16.h>
#include <cstdint>

// ============================================================
// out[b,n] = sum_{c,p} x[b,c,p]*mask[p,c,n]*ro[c,n]
//          = A(256 x 82944) @ W(82944 x 2000),  k = p*64+c
//   A[b,k] = fp16(x[b,c,p])                  (pack kernel)
//   W[k,n] = fp16(mask)*fp16(ro[k&63,n]*1024)  (built on the fly;
//            output scaled by 1/1024)
// R15 (wavefront model validated on R13 ncu: 1088 wf/iter):
//   1. warp tiling 4mx2n -> 2mx4n (warp tile 64m x 32n):
//      B-frag duplication 4x->2x  (-256 wf, +128 A wf)
//   2. build STS via R11's interleaved n (n = nq+32q, stride 68B
//      odd-word -> conflict-free)                  (-192 wf)
//   => 768 wf/iter predicted, gemm ~350us.
// GEMM: mma.sync.m16n8k16 f32-accum, CTA 128m x 128n, KTILE=32,
//      grid 16 x 2 x 9 = 288 CTAs, 2 CTAs/SM.
// ============================================================

constexpr int BB   = 256;
constexpr int CCH  = 64;
constexpr int PPX  = 1296;
constexpr int NN   = 2000;
constexpr int NPAD = 2048;
constexpr long long KT_TOT = 82944;

constexpr int KSPLIT = 9;
constexpr int KSLICE = 9216;                  // 82944/9
constexpr int KTILE  = 32;
constexpr int NKT    = KSLICE / KTILE;        // 288
constexpr int MTILE  = 128;
constexpr int NTILE  = 128;
constexpr int NTX    = 16;

constexpr int SA = 40;                        // A smem stride (halves), 80B rows
constexpr int SB = 34;                        // B smem stride (halves), 68B rows
constexpr int A_ST = MTILE * SA;              // 5120 halves / stage
constexpr int B_ST = NTILE * SB;              // 4352 halves / stage
constexpr int SM_A_BYTES  = 2 * A_ST * 2;     // 20480
constexpr int SM_B_BYTES  = 2 * B_ST * 2;     // 17408
constexpr int SMEM_TOTAL  = SM_A_BYTES + SM_B_BYTES;  // 37888

// ------------- scratch (device globals; no runtime allocs allowed) ----------
__device__ __half g_Ah[(size_t)BB * KT_TOT];               // 42.5 MB
__device__ float  g_part[(size_t)KSPLIT * BB * NPAD];      // 18.9 MB

// ----------------------------- helpers --------------------------------------
__device__ __forceinline__ uint32_t smem_u32(const void* p) {
    uint32_t a;
    asm("{ .reg .u64 t; cvta.to.shared.u64 t, %1; cvt.u32.u64 %0, t; }"
        : "=r"(a) : "l"(p));
    return a;
}
__device__ __forceinline__ uint32_t lds_u32(uint32_t a) {
    uint32_t v;
    asm volatile("ld.shared.b32 %0, [%1];" : "=r"(v) : "r"(a));
    return v;
}
#define STS_U32(addr, v) \
    asm volatile("st.shared.b32 [%0], %1;" :: "r"(addr), "r"(v) : "memory")
#define CP_A16(dst, src) \
    asm volatile("cp.async.cg.shared.global [%0], [%1], 16;" :: "r"(dst), "l"(src))
#define CP_COMMIT() asm volatile("cp.async.commit_group;" ::: "memory")
#define CP_WAIT0()  asm volatile("cp.async.wait_group 0;" ::: "memory")
#define LDSM4(r0, r1, r2, r3, addr) \
    asm volatile("ldmatrix.sync.aligned.m8n8.x4.shared.b16 {%0,%1,%2,%3}, [%4];" \
        : "=r"(r0), "=r"(r1), "=r"(r2), "=r"(r3) : "r"(addr))
#define MMA16816(d0, d1, d2, d3, a0, a1, a2, a3, b0, b1) \
    asm volatile("mma.sync.aligned.m16n8k16.row.col.f32.f16.f16.f32 " \
        "{%0,%1,%2,%3}, {%4,%5,%6,%7}, {%8,%9}, {%0,%1,%2,%3};" \
        : "+f"(d0), "+f"(d1), "+f"(d2), "+f"(d3) \
        : "r"(a0), "r"(a1), "r"(a2), "r"(a3), "r"(b0), "r"(b1))

// ------------------ dummy kernels (shift ncu capture slot onto gemm) --------
__global__ void warm_a_kernel() {}
__global__ void warm_b_kernel() {}

// ------------------ kernel 1: pack x -> Ah[b][p*64+c] (fp16) ----------------
__global__ void pack_x_kernel(const float* __restrict__ x) {
    __shared__ float s[64][65];
    int b = blockIdx.y;
    int p0 = blockIdx.x * 64;
    int tid = threadIdx.x;
    const float* xb = x + (size_t)b * (CCH * PPX);
    #pragma unroll
    for (int it = 0; it < 16; it++) {
        int t = tid + it * 256;
        int c = t >> 6, i = t & 63, p = p0 + i;
        s[c][i] = (p < PPX) ? xb[c * PPX + p] : 0.f;
    }
    __syncthreads();
    __half* ab = g_Ah + (size_t)b * KT_TOT;
    #pragma unroll
    for (int it = 0; it < 16; it++) {
        int t = tid + it * 256;
        int i = t >> 6, c = t & 63, p = p0 + i;
        if (p < PPX) ab[p * 64 + c] = __float2half_rn(s[c][i]);
    }
}

// ------------------ kernel 2: fused fp16 mma.sync GEMM ----------------------
__global__ void __launch_bounds__(256, 2)
gemm_kernel(const float* __restrict__ mask, const float* __restrict__ ro) {
    extern __shared__ __align__(16) unsigned char smraw[];
    __half* As  = reinterpret_cast<__half*>(smraw);
    __half* Bsm = reinterpret_cast<__half*>(smraw + SM_A_BYTES);

    int tid = threadIdx.x, w = tid >> 5, l = tid & 31;
    int n0 = blockIdx.x * NTILE;
    int m0 = blockIdx.y * MTILE;
    long long kbase = (long long)blockIdx.z * KSLICE;

    // B-build mapping (R11 interleaved, PASS-verified): thread (nq, kq)
    // owns n = n0 + nq + 32q (q=0..3), k rows {2kq, 2kq+1, +16}
    int nq = tid & 31, kq = (tid >> 5) & 7;
    bool valq[4];
    #pragma unroll
    for (int q = 0; q < 4; q++) valq[q] = (n0 + nq + 32 * q) < NN;

    // readout in registers: rr0/rr1[it][q] = half2{ro[c0][n], ro[c0+1][n]}*1024
    // c0 = 2kq + 16it (+32 for rr1), n = n0 + nq + 32q
    __half2 rr0[2][4], rr1[2][4];
    #pragma unroll
    for (int it = 0; it < 2; it++) {
        #pragma unroll
        for (int q = 0; q < 4; q++) {
            int n = n0 + nq + 32 * q;
            bool ok = (n < NN);
            int c0 = 2 * kq + 16 * it;
            float a0 = ok ? ro[(size_t)c0 * NN + n] * 1024.f : 0.f;
            float a1 = ok ? ro[(size_t)(c0 + 1) * NN + n] * 1024.f : 0.f;
            float b0 = ok ? ro[(size_t)(c0 + 32) * NN + n] * 1024.f : 0.f;
            float b1 = ok ? ro[(size_t)(c0 + 33) * NN + n] * 1024.f : 0.f;
            rr0[it][q] = __floats2half2_rn(a0, a1);
            rr1[it][q] = __floats2half2_rn(b0, b1);
        }
    }

    // A cp.async mapping: 2 threads per row (row = tid>>1), 32B each
    const __half* arow = g_Ah + (size_t)(m0 + (tid >> 1)) * KT_TOT + kbase
                              + (size_t)((tid & 1) * 16);
    uint32_t sbase = smem_u32(As);
    uint32_t adst  = sbase + (uint32_t)((tid >> 1) * (SA * 2) + (tid & 1) * 32);
    uint32_t bbase = smem_u32(Bsm);

    // mrx[(it*2+h)*4 + q] = mask[kt*32 + 2kq + 16it + h][n0 + nq + 32q]
    float mrx[16];
    auto ldmask = [&](int kt) {
        #pragma unroll
        for (int it = 0; it < 2; it++) {
            #pragma unroll
            for (int h = 0; h < 2; h++) {
                long long krow = kbase + (long long)(kt * KTILE + 2 * kq + 16 * it + h);
                const float* rowp = mask + krow * NN + n0 + nq;
                #pragma unroll
                for (int q = 0; q < 4; q++)
                    mrx[(it * 2 + h) * 4 + q] = valq[q] ? rowp[32 * q] : 0.f;
            }
        }
    };

    // build B tile (layout [n][k], stride SB=34): b32 at (n, k0*2) =
    // {W[k0][n], W[k0+1][n]}.  Lane n-stride 68B (17 words) -> conflict-free.
    auto buildB_impl = [&](int s, const __half2 (&rp)[2][4]) {
        uint32_t bst = bbase + (uint32_t)(s * (B_ST * 2));
        #pragma unroll
        for (int it = 0; it < 2; it++) {
            int k0 = 2 * kq + 16 * it;
            #pragma unroll
            for (int q = 0; q < 4; q++) {
                int nn = nq + 32 * q;
                __half2 mm = __floats2half2_rn(mrx[(it * 2 + 0) * 4 + q],
                                               mrx[(it * 2 + 1) * 4 + q]);
                __half2 hh = __hmul2(mm, rp[it][q]);
                STS_U32(bst + (uint32_t)(nn * (SB * 2)) + (uint32_t)(k0 * 2),
                        *reinterpret_cast<uint32_t*>(&hh));
            }
        }
    };
    auto buildB = [&](int kt, int s) {
        if (kt & 1) buildB_impl(s, rr1);
        else        buildB_impl(s, rr0);
    };

    auto cpA = [&](int kt, int s) {
        uint32_t d = adst + (uint32_t)(s * (A_ST * 2));
        const __half* src = arow + (size_t)kt * KTILE;
        CP_A16(d,      src);
        CP_A16(d + 16, src + 8);
    };

    // ---------------- prologue ---------------------------------------------
    ldmask(0);
    cpA(0, 0); CP_COMMIT();
    buildB(0, 0);          // ro in regs: no barrier needed before build
    ldmask(1);

    // fragment addressing: warp tile 64(m) x 32(n); 2 m-warps x 4 n-warps
    int wm = (w & 1) * 64, wn = (w >> 1) * 32;
    uint32_t aLdsm = sbase + (uint32_t)(((wm + (l & 15)) * SA + ((l & 16) ? 8 : 0)) * 2);
    uint32_t bfrag0 = bbase + (uint32_t)((wn + (l >> 2)) * SB * 2) + (uint32_t)(4 * (l & 3));

    float acc[4][4][4];
    #pragma unroll
    for (int i = 0; i < 4; i++)
        #pragma unroll
        for (int j = 0; j < 4; j++)
            #pragma unroll
            for (int q = 0; q < 4; q++) acc[i][j][q] = 0.f;

    // ---------------- main loop (pipelined: MMA(kt) || build(kt+1)) --------
    for (int kt = 0; kt < NKT; kt++) {
        int s = kt & 1;

        CP_WAIT0();          // A(kt) resident
        __syncthreads();     // publish build(kt) STS + A(kt); fence prior readers

        if (kt + 1 < NKT) {
            cpA(kt + 1, s ^ 1); CP_COMMIT();   // into stage read by MMA(kt-1): safe
            buildB(kt + 1, s ^ 1);             // overlaps MMA(kt) below
        }
        if (kt + 2 < NKT) ldmask(kt + 2);      // refill mrx (consumed above)

        // ---- MMA: warp tile 64(m) x 32(n), 2 ksteps of 16 ----------------
        uint32_t aS = aLdsm + (uint32_t)(s * (A_ST * 2));
        uint32_t bS = bfrag0 + (uint32_t)(s * (B_ST * 2));
        #pragma unroll
        for (int ks = 0; ks < 2; ks++) {
            uint32_t af[4][4];
            #pragma unroll
            for (int i = 0; i < 4; i++)
                LDSM4(af[i][0], af[i][1], af[i][2], af[i][3],
                      aS + (uint32_t)(i * 16 * SA * 2) + (uint32_t)(ks * 32));
            #pragma unroll
            for (int j = 0; j < 4; j++) {
                uint32_t ba = bS + (uint32_t)(j * 8 * SB * 2) + (uint32_t)(ks * 32);
                uint32_t b0 = lds_u32(ba);
                uint32_t b1 = lds_u32(ba + 16);
                #pragma unroll
                for (int i = 0; i < 4; i++)
                    MMA16816(acc[i][j][0], acc[i][j][1], acc[i][j][2], acc[i][j][3],
                             af[i][0], af[i][1], af[i][2], af[i][3], b0, b1);
            }
        }
    }

    // ---- epilogue: fp32 partials ------------------------------------------
    float* __restrict__ part = g_part + (size_t)blockIdx.z * BB * NPAD;
    int r0 = l >> 2, cq = 2 * (l & 3);
    #pragma unroll
    for (int i = 0; i < 4; i++) {
        #pragma unroll
        for (int j = 0; j < 4; j++) {
            int m = m0 + wm + 16 * i + r0;
            int n = wn + 8 * j + cq + n0;
            *reinterpret_cast<float2*>(part + (size_t)m * NPAD + n) =
                make_float2(acc[i][j][0], acc[i][j][1]);
            *reinterpret_cast<float2*>(part + (size_t)(m + 8) * NPAD + n) =
                make_float2(acc[i][j][2], acc[i][j][3]);
        }
    }
}

// ------------------ kernel 3: reduce partials -> out (x 1/1024) -------------
__global__ void reduce_kernel(float* __restrict__ out) {
    int id = blockIdx.x * 256 + threadIdx.x;          // id indexes (b, n4)
    int b = id / (NPAD / 4), n4 = id % (NPAD / 4);
    if (b >= BB) return;
    int n = n4 * 4;
    float4 s = make_float4(0.f, 0.f, 0.f, 0.f);
    #pragma unroll
    for (int ks = 0; ks < KSPLIT; ks++) {
        const float4 v = *reinterpret_cast<const float4*>(
            g_part + (size_t)ks * BB * NPAD + (size_t)b * NPAD + n);
        s.x += v.x; s.y += v.y; s.z += v.z; s.w += v.w;
    }
    const float inv = 1.f / 1024.f;
    float* o = out + (size_t)b * NN;
    if (n + 3 < NN) {
        o[n] = s.x * inv; o[n + 1] = s.y * inv; o[n + 2] = s.z * inv; o[n + 3] = s.w * inv;
    } else {
        if (n < NN)     o[n]     = s.x * inv;
        if (n + 1 < NN) o[n + 1] = s.y * inv;
        if (n + 2 < NN) o[n + 2] = s.z * inv;
        if (n + 3 < NN) o[n + 3] = s.w * inv;
    }
}

// ------------------------------- host ---------------------------------------
extern "C" void kernel_launch(void* const* d_in, const int* in_sizes, int n_in,
                              void* d_out, int out_size) {
    const float* x = nullptr;
    const float* mw = nullptr;
    const float* ro = nullptr;
    for (int i = 0; i < n_in; i++) {
        long long sz = in_sizes[i];
        if (sz == (long long)BB * CCH * PPX)      x  = (const float*)d_in[i];
        else if (sz == (long long)PPX * CCH * NN) mw = (const float*)d_in[i];
        else if (sz == (long long)CCH * NN)       ro = (const float*)d_in[i];
    }

    cudaFuncSetAttribute(gemm_kernel, cudaFuncAttributeMaxDynamicSharedMemorySize,
                         SMEM_TOTAL);

    warm_a_kernel<<<1, 32>>>();
    warm_b_kernel<<<1, 32>>>();
    pack_x_kernel<<<dim3(21, BB), 256>>>(x);
    gemm_kernel<<<dim3(NTX, BB / MTILE, KSPLIT), 256, SMEM_TOTAL>>>(mw, ro);
    reduce_kernel<<<(BB * (NPAD / 4) + 255) / 256, 256>>>((float*)d_out);
}